// round 17
// baseline (speedup 1.0000x reference)
#include <cuda_runtime.h>
#include <cuda.h>
#include <cuda_bf16.h>
#include <cstdint>

#define PH    16
#define PW    16
#define NM    16
#define HDIM  224
#define WDIM  224
#define CDIM  64
#define HW    (HDIM * WDIM)
#define NBUF  4
#define CCH   8                   // channels per chunk
#define NCHK  (CDIM / CCH)        // 8 chunks
#define SW    32                  // strip width (2 patches)
#define SPIX  (SW * PH)           // 512 pixels
#define CHUNK_BYTES (CCH * SPIX * 4)   // 16 KB
#define NSW   7                   // strips per row

// dynamic smem layout (kernel A)
#define OFF_BUF   0
#define OFF_MBAR  (NBUF * CHUNK_BYTES)          // 65536
#define OFF_RED   (OFF_MBAR + NBUF * 8)         // 65568
#define SMEM_DYN  69632                          // 68 KB -> 3 CTAs/SM

// coefficient scratch: [b][hy][wx][patch][m]  (1568 strips * 32 floats = 200KB)
__device__ float g_coef[16 * 14 * NSW * 2 * NM];

__device__ __forceinline__ uint32_t smem_u32(const void* p) {
    uint32_t a;
    asm("{ .reg .u64 t; cvta.to.shared.u64 t, %1; cvt.u32.u64 %0, t; }"
        : "=r"(a) : "l"(p));
    return a;
}
__device__ __forceinline__ void mbar_init(uint32_t a, uint32_t cnt) {
    asm volatile("mbarrier.init.shared.b64 [%0], %1;" :: "r"(a), "r"(cnt) : "memory");
}
__device__ __forceinline__ void mbar_expect_tx(uint32_t a, uint32_t bytes) {
    asm volatile("mbarrier.arrive.expect_tx.shared.b64 _, [%0], %1;"
                 :: "r"(a), "r"(bytes) : "memory");
}
__device__ __forceinline__ void mbar_wait(uint32_t a, uint32_t phase) {
    asm volatile(
        "{\n\t.reg .pred P;\n"
        "W_%=:\n\t"
        "mbarrier.try_wait.parity.acquire.cta.shared::cta.b64 P, [%0], %1, 0x989680;\n\t"
        "@P bra D_%=;\n\t"
        "bra W_%=;\n"
        "D_%=:\n\t}"
        :: "r"(a), "r"(phase) : "memory");
}
__device__ __forceinline__ uint64_t mk_policy_ef() {
    uint64_t pol;
    asm volatile("createpolicy.fractional.L2::evict_first.b64 %0, 1.0;" : "=l"(pol));
    return pol;
}
__device__ __forceinline__ void tma_ld3d_ef(uint32_t dst, const CUtensorMap* m,
                                            int cx, int cy, int cz, uint32_t mbar,
                                            uint64_t pol) {
    asm volatile(
        "cp.async.bulk.tensor.3d.shared::cta.global.tile.mbarrier::complete_tx::bytes"
        ".L2::cache_hint [%0], [%1, {%2, %3, %4}], [%5], %6;"
        :: "r"(dst), "l"(m), "r"(cx), "r"(cy), "r"(cz), "r"(mbar), "l"(pol)
        : "memory");
}
// 256-bit store (valid hint-free v8 form not required; plain v8 via two stcs)
__device__ __forceinline__ void stcs8(float* p, float v) {
    const float4 vv = make_float4(v, v, v, v);
    __stcs(reinterpret_cast<float4*>(p), vv);
    __stcs(reinterpret_cast<float4*>(p) + 1, vv);
}

// ====== Kernel A: pure-read TMA coefficient kernel (R14 read engine) ======
__global__ __launch_bounds__(512, 3)
void msp_coef_kernel(const __grid_constant__ CUtensorMap tmap,
                     const float* __restrict__ bases) {
    extern __shared__ char dyn[];
    float* sBuf  = reinterpret_cast<float*>(dyn + OFF_BUF);
    unsigned long long* mbar = reinterpret_cast<unsigned long long*>(dyn + OFF_MBAR);
    float* sRed  = reinterpret_cast<float*>(dyn + OFF_RED);   // 32 groups x 16

    const int t   = threadIdx.x;           // t = row*32 + col
    const int wx  = blockIdx.x;            // 0..6
    const int hy  = blockIdx.y;            // 0..13
    const int b   = blockIdx.z;            // 0..15
    const int cb  = b * CDIM;

    if (t == 0) {
        #pragma unroll
        for (int i = 0; i < NBUF; i++) mbar_init(smem_u32(&mbar[i]), 1);
        asm volatile("fence.proxy.async.shared::cta;" ::: "memory");
    }
    __syncthreads();

    uint64_t pol = 0;
    if (t == 0) {
        pol = mk_policy_ef();
        #pragma unroll
        for (int i = 0; i < NBUF; i++) {
            mbar_expect_tx(smem_u32(&mbar[i]), CHUNK_BYTES);
            tma_ld3d_ef(smem_u32(&sBuf[i * CCH * SPIX]), &tmap,
                        wx * SW, hy * PH, cb + i * CCH, smem_u32(&mbar[i]), pol);
        }
    }

    float sum = 0.f;
    #pragma unroll
    for (int k = 0; k < NCHK; k++) {
        const int slot = k & (NBUF - 1);
        mbar_wait(smem_u32(&mbar[slot]), (k >> 2) & 1);
        const float* buf = &sBuf[slot * CCH * SPIX];
        #pragma unroll
        for (int j = 0; j < CCH; j++)
            sum += buf[j * SPIX + t];
        __syncthreads();
        if (k + NBUF < NCHK && t == 0) {
            mbar_expect_tx(smem_u32(&mbar[slot]), CHUNK_BYTES);
            tma_ld3d_ef(smem_u32(&sBuf[slot * CCH * SPIX]), &tmap,
                        wx * SW, hy * PH, cb + (k + NBUF) * CCH,
                        smem_u32(&mbar[slot]), pol);
        }
    }

    const int warp = t >> 5;
    const int lane = t & 31;
    const int pb   = warp * 16 + (lane & 15);
    #pragma unroll
    for (int half = 0; half < 2; half++) {
        float part[8];
        #pragma unroll
        for (int m = 0; m < 8; m++)
            part[m] = sum * __ldg(bases + (half * 8 + m) * 256 + pb);
        #pragma unroll
        for (int m = 0; m < 8; m++) {
            part[m] += __shfl_xor_sync(0xffffffffu, part[m], 1);
            part[m] += __shfl_xor_sync(0xffffffffu, part[m], 2);
            part[m] += __shfl_xor_sync(0xffffffffu, part[m], 4);
            part[m] += __shfl_xor_sync(0xffffffffu, part[m], 8);
        }
        if ((lane & 15) == 0) {
            const int pidx = lane >> 4;
            #pragma unroll
            for (int m = 0; m < 8; m++)
                sRed[(warp * 2 + pidx) * NM + half * 8 + m] = part[m];
        }
    }
    __syncthreads();
    if (t < 32) {
        const int m = t & 15, pidx = t >> 4;
        float c = 0.f;
        #pragma unroll
        for (int w = 0; w < 16; w++) c += sRed[(w * 2 + pidx) * NM + m];
        const int strip = (b * 14 + hy) * NSW + wx;
        g_coef[strip * 32 + pidx * NM + m] = c * (1.0f / (float)CDIM);
    }
}

// ====== Kernel B: pure-write broadcast, 512 thr/strip, 2x 32B stores each ====
__global__ __launch_bounds__(512, 4)
void msp_bcast_kernel(float* __restrict__ out) {
    __shared__ float sCoef[32];

    const int t  = threadIdx.x;
    const int wx = blockIdx.x;
    const int hy = blockIdx.y;
    const int b  = blockIdx.z;
    const int h0 = hy * PH;
    const int w0 = wx * SW;

    if (t < 32) {
        const int strip = (b * 14 + hy) * NSW + wx;
        sCoef[t] = g_coef[strip * 32 + t];
    }
    __syncthreads();

    // 1024 output octets (32B) per strip: idx = m*64 + row*4 + colOct
    #pragma unroll
    for (int k = 0; k < 2; k++) {
        const int idx = t + k * 512;
        const int m   = idx >> 6;            // base 0..15
        const int gg  = idx & 63;
        const int rr  = gg >> 2;             // row 0..15
        const int co  = (gg & 3) * 8;        // col 0,8,16,24
        const float v = sCoef[(co >> 4) * NM + m];
        float* o = out + ((size_t)(b * NM + m) * HDIM + (h0 + rr)) * WDIM
                       + (w0 + co);
        stcs8(o, v);
    }
}

// ============ fallback: R3 LDG kernel (proven 45.5us) ============
__global__ __launch_bounds__(256, 6)
void msp_dct_ldg_kernel(const float* __restrict__ x,
                        const float* __restrict__ bases,
                        float* __restrict__ out) {
    __shared__ float4 sPart[256];
    __shared__ float  sW[2][NM];
    __shared__ float  sCoef[NM];

    const int t  = threadIdx.x;
    const int pw = blockIdx.x;
    const int ph = blockIdx.y;
    const int b  = blockIdx.z;
    const int h0 = ph * PH;
    const int w0 = pw * PW;

    const int g   = t & 63;
    const int pi  = g >> 2;
    const int pj4 = (g & 3) * 4;
    const int csl = t >> 6;
    {
        const float* p = x + ((size_t)(b * CDIM + csl * 16)) * HW
                           + (size_t)(h0 + pi) * WDIM + (w0 + pj4);
        float4 acc = make_float4(0.f, 0.f, 0.f, 0.f);
        #pragma unroll
        for (int cc = 0; cc < 16; cc++) {
            const float4 v = __ldcs(reinterpret_cast<const float4*>(p + (size_t)cc * HW));
            acc.x += v.x; acc.y += v.y; acc.z += v.z; acc.w += v.w;
        }
        sPart[t] = acc;
    }
    __syncthreads();

    if (t < 64) {
        const float4 a0 = sPart[t];
        const float4 a1 = sPart[t + 64];
        const float4 a2 = sPart[t + 128];
        const float4 a3 = sPart[t + 192];
        float4 m4;
        m4.x = a0.x + a1.x + a2.x + a3.x;
        m4.y = a0.y + a1.y + a2.y + a3.y;
        m4.z = a0.z + a1.z + a2.z + a3.z;
        m4.w = a0.w + a1.w + a2.w + a3.w;

        const int pb = pi * 16 + pj4;
        float part[NM];
        #pragma unroll
        for (int m = 0; m < NM; m++) {
            const float4 bq = __ldg(reinterpret_cast<const float4*>(bases + m * 256 + pb));
            part[m] = m4.x * bq.x + m4.y * bq.y + m4.z * bq.z + m4.w * bq.w;
        }
        #pragma unroll
        for (int m = 0; m < NM; m++) {
            #pragma unroll
            for (int off = 16; off; off >>= 1)
                part[m] += __shfl_xor_sync(0xffffffffu, part[m], off);
        }
        if ((t & 31) == 0) {
            const int w = t >> 5;
            #pragma unroll
            for (int m = 0; m < NM; m++) sW[w][m] = part[m];
        }
    }
    __syncthreads();
    if (t < NM) sCoef[t] = (sW[0][t] + sW[1][t]) * (1.0f / (float)CDIM);
    __syncthreads();

    #pragma unroll
    for (int k = 0; k < 4; k++) {
        const int idx = t + k * 256;
        const int m   = idx >> 6;
        const int gg  = idx & 63;
        const int ii  = gg >> 2;
        const int jj  = (gg & 3) * 4;
        const float v = sCoef[m];
        float* o = out + ((size_t)(b * NM + m) * HDIM + (h0 + ii)) * WDIM
                       + (w0 + jj);
        __stcs(reinterpret_cast<float4*>(o), make_float4(v, v, v, v));
    }
}

// ---------------- host ----------------
typedef CUresult (*EncodeFn)(CUtensorMap*, CUtensorMapDataType, cuuint32_t, void*,
                             const cuuint64_t*, const cuuint64_t*, const cuuint32_t*,
                             const cuuint32_t*, CUtensorMapInterleave, CUtensorMapSwizzle,
                             CUtensorMapL2promotion, CUtensorMapFloatOOBfill);

extern "C" void kernel_launch(void* const* d_in, const int* in_sizes, int n_in,
                              void* d_out, int out_size) {
    const float* x     = (const float*)d_in[0];
    const float* bases = (const float*)d_in[1];
    float*       out   = (float*)d_out;

    void* fp = nullptr;
    cudaDriverEntryPointQueryResult qr;
    cudaGetDriverEntryPoint("cuTensorMapEncodeTiled", &fp, cudaEnableDefault, &qr);

    bool ok = (fp != nullptr);
    CUtensorMap tmap;
    if (ok) {
        cuuint64_t dims[3]    = {WDIM, HDIM, 16 * CDIM};
        cuuint64_t strides[2] = {WDIM * 4ull, (cuuint64_t)HW * 4ull};
        cuuint32_t box[3]     = {SW, PH, CCH};
        cuuint32_t es[3]      = {1, 1, 1};
        ok = (((EncodeFn)fp)(&tmap, CU_TENSOR_MAP_DATA_TYPE_FLOAT32, 3, (void*)x,
                             dims, strides, box, es,
                             CU_TENSOR_MAP_INTERLEAVE_NONE, CU_TENSOR_MAP_SWIZZLE_NONE,
                             CU_TENSOR_MAP_L2_PROMOTION_L2_256B,
                             CU_TENSOR_MAP_FLOAT_OOB_FILL_NONE) == CUDA_SUCCESS);
    }
    if (ok) {
        ok = (cudaFuncSetAttribute(msp_coef_kernel,
                                   cudaFuncAttributeMaxDynamicSharedMemorySize,
                                   SMEM_DYN) == cudaSuccess);
    }

    if (ok) {
        dim3 grid(NSW, 14, 16);              // 7 x 14 x 16 = 1568 strips
        msp_coef_kernel<<<grid, 512, SMEM_DYN>>>(tmap, bases);
        msp_bcast_kernel<<<grid, 512>>>(out);
    } else {
        dim3 grid(WDIM / PW, HDIM / PH, 16);
        msp_dct_ldg_kernel<<<grid, 256>>>(x, bases, out);
    }
}